// round 12
// baseline (speedup 1.0000x reference)
#include <cuda_runtime.h>
#include <math.h>

#define NBATCH 2048

// ---- image layout: skewed rows ----
// row ry = y+2 (0..66); rowbase(ry) = ry*72 + ((ry>>2)<<2)  (skew keeps float4
// alignment and spreads the per-oy bank start: for conv1 row ry=4*oy+ky the
// skew term is 4*(oy + (ky>>2)) -> lane starts 4*(oy+c) mod 32: 8 distinct).
// pixel x stored at float index rowbase + x + 2; taps of ox = floats 4*ox..4*ox+10.
#define IMCH  4884                  // covers 66*72 + 64 + 68, mult of 4
#define S_W1  (3 * IMCH)            // 14652; conv1 weights [c][ky][f][12] = 3960
#define SMEM_FLOATS (S_W1 + 3960)   // 18612 floats = 74448 bytes -> 3 CTAs/SM

// aliases in the image region (dead after conv1 mainloop):
#define S_TMP  0                    // group-B partials [10][15][16] = 2400
#define S_C1   2400                 // conv1 out [10][15][16] = 2400
#define S_W2P  4800                 // conv2 weights padded [16][10][5][8] = 6400
#define S_P1P  11200                // pool1 out zero-padded [10][11][12] = 1320
#define S_C2   12520                // conv2 out [16][4][4] = 256
#define S_FL   12776                // flat 64

__device__ __forceinline__ float leaky(float v) { return v > 0.f ? v : 0.01f * v; }

__global__ void __launch_bounds__(256, 3)
cnn_kernel(const float* __restrict__ im,
           const float* __restrict__ w1,
           const float* __restrict__ w2,
           const float* __restrict__ b2,
           const float* __restrict__ lw,
           const float* __restrict__ lb,
           float* __restrict__ out)
{
    extern __shared__ float sm[];
    const int b   = blockIdx.x;
    const int tid = threadIdx.x;

    // ---- zero image + weight regions (halo, skew gaps, pad lanes) ----
    for (int i = tid; i < SMEM_FLOATS; i += 256) sm[i] = 0.f;
    __syncthreads();

    {
        const float2* gim = (const float2*)(im + (size_t)b * 12288);
        for (int i = tid; i < 6144; i += 256) {
            float2 v = gim[i];
            int fi = i << 1;
            int c  = fi >> 12;
            int y  = (fi & 4095) >> 6;
            int x  = fi & 63;
            int ry = y + 2;
            int base = c * IMCH + ry * 72 + ((ry >> 2) << 2) + x + 2;
            sm[base]     = v.x;
            sm[base + 1] = v.y;
        }
    }
    // conv1 weights: [f][c][ky][kx] -> [c][ky][f][12] (pad lane kx=11 stays 0)
    for (int i = tid; i < 3630; i += 256) {
        int f   = i / 363;
        int rem = i % 363;
        int c   = rem / 121;
        int r2  = rem % 121;
        int ky  = r2 / 11;
        int kx  = r2 % 11;
        sm[S_W1 + ((c * 11 + ky) * 10 + f) * 12 + kx] = w1[i];
    }

    // graph half is analytically constant: softmax == 0.05 (verified exact R1-R11)
    if (tid < 20)
        out[b * 20 + tid] = 0.05f;

    __syncthreads();

    // ---- conv1 (11x11, s4, p2): 15x15 out, 10 filters ----
    // K-split: group A = tid 0-59 (warps 0-1), rows m=c*11+ky in [0,16)
    //          group B = tid 64-123 (warps 2-3), rows m in [16,33)
    // thread a: oy = a%15, g = a/15; pixels ox = 4g+d (d=0..3, ox=15 discarded)
    // chunk-dot: acc[f][d] += dot(X4[d+q], W4[f][q]); 6 input LDS.128/row,
    // weights warp-uniform (broadcast, no conflict cost).
    const bool grpA = (tid < 60);
    const bool grpB = (tid >= 64 && tid < 124);
    const bool c1act = grpA || grpB;
    const int  a  = grpA ? tid : (tid - 64);
    const int  oy = a % 15, g = a / 15;
    const int  mstart = grpA ? 0 : 16;
    const int  mend   = grpA ? 16 : 33;

    float acc[10][4];
    #pragma unroll
    for (int f = 0; f < 10; f++)
        #pragma unroll
        for (int d = 0; d < 4; d++) acc[f][d] = 0.f;

    if (c1act) {
        #pragma unroll 1
        for (int m = mstart; m < mend; m++) {
            const int c = m / 11, ky = m % 11;
            const int ry = 4 * oy + ky;
            const float4* Xp = (const float4*)
                &sm[c * IMCH + ry * 72 + ((ry >> 2) << 2) + 16 * g];
            float4 X[6];
            #pragma unroll
            for (int j = 0; j < 6; j++) X[j] = Xp[j];
            const float4* wp = (const float4*)&sm[S_W1 + (m * 10) * 12];
            #pragma unroll
            for (int f = 0; f < 10; f++) {
                #pragma unroll
                for (int q = 0; q < 3; q++) {
                    float4 w = wp[f * 3 + q];
                    #pragma unroll
                    for (int d = 0; d < 4; d++) {
                        float4 x = X[d + q];
                        float s = acc[f][d];
                        s = fmaf(x.x, w.x, s);
                        s = fmaf(x.y, w.y, s);
                        s = fmaf(x.z, w.z, s);
                        s = fmaf(x.w, w.w, s);
                        acc[f][d] = s;
                    }
                }
            }
        }
    }
    __syncthreads();   // image reads done; region reusable

    // group B parks raw partials (float4: d=0..3 contiguous at 16g)
    if (grpB) {
        #pragma unroll
        for (int f = 0; f < 10; f++)
            *(float4*)&sm[S_TMP + (f * 15 + oy) * 16 + 4 * g] =
                make_float4(acc[f][0], acc[f][1], acc[f][2], acc[f][3]);
    }
    // stage conv2 weights padded [f][c][ky][8]
    for (int i = tid; i < 4000; i += 256) {
        int kx = i % 5; int t = i / 5;
        int ky = t % 5; t /= 5;
        int c  = t % 10; int f = t / 10;
        sm[S_W2P + (((f * 10 + c) * 5) + ky) * 8 + kx] = w2[i];
    }
    // zero-fill padded pool1 buffer
    for (int i = tid; i < 1320; i += 256)
        sm[S_P1P + i] = 0.f;
    __syncthreads();

    // group A combines + leaky -> C1
    if (grpA) {
        #pragma unroll
        for (int f = 0; f < 10; f++) {
            float4 p = *(const float4*)&sm[S_TMP + (f * 15 + oy) * 16 + 4 * g];
            float r0 = leaky(acc[f][0] + p.x);
            float r1 = leaky(acc[f][1] + p.y);
            float r2 = leaky(acc[f][2] + p.z);
            float r3 = leaky(acc[f][3] + p.w);
            *(float4*)&sm[S_C1 + (f * 15 + oy) * 16 + 4 * g] =
                make_float4(r0, r1, r2, r3);   // ox=15 slot unused by pool (stride-16 pad col)
        }
    }
    __syncthreads();

    // ---- maxpool 3x3 s2: 15x15 -> 7x7, write into zero-padded [10][11][12] ----
    for (int i = tid; i < 490; i += 256) {
        int f = i / 49, r = i % 49;
        int py = r / 7, px = r % 7;
        float m = -1e30f;
        #pragma unroll
        for (int dy = 0; dy < 3; dy++)
            #pragma unroll
            for (int dx = 0; dx < 3; dx++)
                m = fmaxf(m, sm[S_C1 + (f * 15 + (2 * py + dy)) * 16 + (2 * px + dx)]);
        sm[S_P1P + (f * 11 + py + 2) * 12 + px + 2] = m;
    }
    __syncthreads();

    // ---- conv2 (5x5, s2, p2): 7x7 -> 4x4, 10 -> 16 ch, guard-free ----
    {
        int f   = tid >> 4;
        int r   = tid & 15;
        int oy2 = r >> 2;
        int ox2 = r & 3;
        float av = b2[f];
        #pragma unroll 1
        for (int c = 0; c < 10; c++) {
            #pragma unroll
            for (int ky = 0; ky < 5; ky++) {
                const float* prow = &sm[S_P1P + (c * 11 + 2 * oy2 + ky) * 12 + 2 * ox2];
                const float4 wv = *(const float4*)&sm[S_W2P + ((f * 10 + c) * 5 + ky) * 8];
                const float  w4 = sm[S_W2P + ((f * 10 + c) * 5 + ky) * 8 + 4];
                av = fmaf(prow[0], wv.x, av);
                av = fmaf(prow[1], wv.y, av);
                av = fmaf(prow[2], wv.z, av);
                av = fmaf(prow[3], wv.w, av);
                av = fmaf(prow[4], w4,  av);
            }
        }
        sm[S_C2 + f * 16 + oy2 * 4 + ox2] = leaky(av);
    }
    __syncthreads();

    // ---- maxpool 2x2 s2: 4x4 -> 2x2, flatten ----
    if (tid < 64) {
        int f = tid >> 2, py = (tid >> 1) & 1, px = tid & 1;
        float m = sm[S_C2 + f * 16 + (2 * py) * 4 + (2 * px)];
        m = fmaxf(m, sm[S_C2 + f * 16 + (2 * py) * 4 + (2 * px + 1)]);
        m = fmaxf(m, sm[S_C2 + f * 16 + (2 * py + 1) * 4 + (2 * px)]);
        m = fmaxf(m, sm[S_C2 + f * 16 + (2 * py + 1) * 4 + (2 * px + 1)]);
        sm[S_FL + tid] = m;   // flat index == tid
    }
    __syncthreads();

    // ---- linear 64 -> 2 + sigmoid ----
    if (tid < 2) {
        float a2 = lb[tid];
        #pragma unroll
        for (int k = 0; k < 64; k++)
            a2 = fmaf(sm[S_FL + k], lw[tid * 64 + k], a2);
        out[NBATCH * 20 + b * 2 + tid] = 1.f / (1.f + __expf(-a2));
    }
}

extern "C" void kernel_launch(void* const* d_in, const int* in_sizes, int n_in,
                              void* d_out, int out_size)
{
    (void)in_sizes; (void)n_in; (void)out_size;
    const float* im = (const float*)d_in[0];
    // d_in[1] = x, d_in[2] = edge_index : dead (graph output is constant 0.05)
    const float* w1 = (const float*)d_in[3];
    const float* w2 = (const float*)d_in[4];
    const float* b2 = (const float*)d_in[5];
    const float* lw = (const float*)d_in[6];
    const float* lb = (const float*)d_in[7];
    float* out = (float*)d_out;

    cudaFuncSetAttribute(cnn_kernel, cudaFuncAttributeMaxDynamicSharedMemorySize,
                         SMEM_FLOATS * sizeof(float));
    cnn_kernel<<<NBATCH, 256, SMEM_FLOATS * sizeof(float)>>>(im, w1, w2, b2, lw, lb, out);
}